// round 6
// baseline (speedup 1.0000x reference)
#include <cuda_runtime.h>
#include <math.h>

#define T_TOK 8192
#define HD    2048
#define NE    8
#define ID    1408
#define TWO_I 2816
#define NA    16384
#define NA_PAD 17408   // 16384 + 8*128: per-expert regions aligned to 128 rows
#define MAX_TILES 144
#define RT_TILES 136   // fixed routed-tile grid slots; shared tiles start here

// ---------------- scratch (device globals; no allocation allowed) ----------------
__device__ float g_xin[(size_t)NA_PAD * HD];       // tf32(x*p), expert-grouped
__device__ float g_hidden[(size_t)NA_PAD * ID];    // tf32 routed swiglu
__device__ float g_shidden[(size_t)T_TOK * ID];    // tf32 shared swiglu
// tf32-rounded mirrors (conversion hoisted out of GEMM inner loops)
__device__ float g_xt[(size_t)T_TOK * HD];
__device__ float g_wgu_t[(size_t)NE * HD * TWO_I];
__device__ float g_wd_t[(size_t)NE * ID * HD];
__device__ float g_wsgu_t[(size_t)HD * TWO_I];
__device__ float g_wsd_t[(size_t)ID * HD];
__device__ int   g_top_e[NA];
__device__ float g_top_p[NA];
__device__ float g_gate[T_TOK];
__device__ int   g_cnt[NE], g_off[NE], g_fill[NE];
__device__ int   g_row_token[NA_PAD];
__device__ int   g_tile_e[MAX_TILES], g_tile_row0[MAX_TILES], g_tile_rows[MAX_TILES];
__device__ int   g_ntiles;

// ---------------- helpers ----------------
__device__ __forceinline__ float to_tf32(float f) {
    unsigned u;
    asm("cvt.rna.tf32.f32 %0, %1;" : "=r"(u) : "f"(f));
    return __uint_as_float(u);
}

__device__ __forceinline__ void mma_tf32(float* c, const float* a, float b0, float b1) {
    asm volatile(
        "mma.sync.aligned.m16n8k8.row.col.f32.tf32.tf32.f32 "
        "{%0,%1,%2,%3}, {%4,%5,%6,%7}, {%8,%9}, {%0,%1,%2,%3};\n"
        : "+f"(c[0]), "+f"(c[1]), "+f"(c[2]), "+f"(c[3])
        : "r"(__float_as_uint(a[0])), "r"(__float_as_uint(a[1])),
          "r"(__float_as_uint(a[2])), "r"(__float_as_uint(a[3])),
          "r"(__float_as_uint(b0)),  "r"(__float_as_uint(b1)));
}

__device__ __forceinline__ void cp16(void* dst, const void* src) {
    unsigned d = (unsigned)__cvta_generic_to_shared(dst);
    asm volatile("cp.async.cg.shared.global [%0], [%1], 16;\n" :: "r"(d), "l"(src));
}
__device__ __forceinline__ void cp_commit() { asm volatile("cp.async.commit_group;\n"); }
__device__ __forceinline__ void cp_wait1()  { asm volatile("cp.async.wait_group 1;\n"); }

// ---------------- small kernels ----------------
__global__ void init_kernel() {
    int t = threadIdx.x;
    if (t < NE) { g_cnt[t] = 0; g_fill[t] = 0; }
}

// tf32-round a tensor (vectorized grid-stride)
__global__ void cvt_kernel(const float4* __restrict__ src, float4* __restrict__ dst, int n4) {
    int i = blockIdx.x * blockDim.x + threadIdx.x;
    int stride = gridDim.x * blockDim.x;
    for (; i < n4; i += stride) {
        float4 v = src[i];
        v.x = to_tf32(v.x); v.y = to_tf32(v.y);
        v.z = to_tf32(v.z); v.w = to_tf32(v.w);
        dst[i] = v;
    }
}

__global__ void router_kernel(const float* __restrict__ x,
                              const float* __restrict__ wr,
                              const float* __restrict__ wsg) {
    int gw   = (blockIdx.x * blockDim.x + threadIdx.x) >> 5;
    int lane = threadIdx.x & 31;
    if (gw >= T_TOK) return;
    const float* xr = x + (size_t)gw * HD;
    float acc[NE];
#pragma unroll
    for (int e = 0; e < NE; e++) acc[e] = 0.f;
    float ag = 0.f;
    for (int h = lane; h < HD; h += 32) {
        float xv = xr[h];
        const float4* w = (const float4*)(wr + (size_t)h * NE);
        float4 w0 = w[0], w1 = w[1];
        acc[0] += xv * w0.x; acc[1] += xv * w0.y; acc[2] += xv * w0.z; acc[3] += xv * w0.w;
        acc[4] += xv * w1.x; acc[5] += xv * w1.y; acc[6] += xv * w1.z; acc[7] += xv * w1.w;
        ag += xv * wsg[h];
    }
#pragma unroll
    for (int o = 16; o > 0; o >>= 1) {
#pragma unroll
        for (int e = 0; e < NE; e++) acc[e] += __shfl_xor_sync(0xffffffffu, acc[e], o);
        ag += __shfl_xor_sync(0xffffffffu, ag, o);
    }
    if (lane == 0) {
        int i0 = 0; float v0 = acc[0];
#pragma unroll
        for (int e = 1; e < NE; e++) if (acc[e] > v0) { v0 = acc[e]; i0 = e; }
        int i1 = -1; float v1 = -1e30f;
#pragma unroll
        for (int e = 0; e < NE; e++) if (e != i0 && acc[e] > v1) { v1 = acc[e]; i1 = e; }
        float t  = __expf(v1 - v0);
        float p0 = 1.f / (1.f + t);
        float p1 = t  / (1.f + t);
        g_top_e[gw * 2]     = i0;
        g_top_e[gw * 2 + 1] = i1;
        g_top_p[gw * 2]     = p0;
        g_top_p[gw * 2 + 1] = p1;
        atomicAdd(&g_cnt[i0], 1);
        atomicAdd(&g_cnt[i1], 1);
        g_gate[gw] = 1.f / (1.f + __expf(-ag));
    }
}

// Expert regions aligned UP to 128 so no tile straddles two experts (R4 fix).
__global__ void scan_kernel() {
    if (threadIdx.x == 0 && blockIdx.x == 0) {
        int off = 0, nt = 0;
        for (int e = 0; e < NE; e++) {
            g_off[e] = off;
            int c = g_cnt[e];
            for (int r = 0; r < c; r += 128) {
                g_tile_e[nt]    = e;
                g_tile_row0[nt] = off + r;
                g_tile_rows[nt] = (c - r < 128) ? (c - r) : 128;
                nt++;
            }
            off = (off + c + 127) & ~127;
        }
        g_ntiles = nt;
    }
}

// copy tf32(x[t]*p) into the expert-grouped buffer
__global__ void scatter_kernel(const float* __restrict__ x) {
    int a = blockIdx.x;
    int t = a >> 1;
    __shared__ int srow;
    int   e = g_top_e[a];
    float p = g_top_p[a];
    if (threadIdx.x == 0) {
        int pos = atomicAdd(&g_fill[e], 1);
        int row = g_off[e] + pos;
        g_row_token[row] = t;
        srow = row;
    }
    __syncthreads();
    int row = srow;
    const float4* src = (const float4*)(x + (size_t)t * HD);
    float4*       dst = (float4*)(g_xin + (size_t)row * HD);
    for (int i = threadIdx.x; i < HD / 4; i += blockDim.x) {
        float4 v = src[i];
        v.x = to_tf32(v.x * p); v.y = to_tf32(v.y * p);
        v.z = to_tf32(v.z * p); v.w = to_tf32(v.w * p);
        dst[i] = v;
    }
}

// ---------------- GEMM1: X @ W_gate_up, fused SwiGLU, cp.async 2-stage ----------------
// All operands pre-rounded to tf32 — inner loop is pure LDS+MMA.
#define AS_STR 20
#define BG_STR 72
__global__ __launch_bounds__(256, 2) void gemm1_kernel(const float* __restrict__ wgu,
                                                       const float* __restrict__ wsgu) {
    int bx = blockIdx.x;
    bool sh = (bx >= RT_TILES);
    int row0;
    const float* A;
    const float* B;
    float* Hout;
    if (sh) {
        row0 = (bx - RT_TILES) * 128;
        A = g_xt; B = wsgu; Hout = g_shidden;
    } else {
        if (bx >= g_ntiles) return;
        row0 = g_tile_row0[bx];
        A = g_xin;
        B = wgu + (size_t)g_tile_e[bx] * HD * TWO_I;
        Hout = g_hidden;
    }
    int col0 = blockIdx.y * 64;

    __shared__ float As[2][128][AS_STR];
    __shared__ float Bg[2][16][BG_STR];
    __shared__ float Bu[2][16][BG_STR];

    int tid = threadIdx.x, lane = tid & 31, warp = tid >> 5;
    int wm = warp >> 1, wn = warp & 1;

    float cg[2][4][4], cu[2][4][4];
#pragma unroll
    for (int i = 0; i < 2; i++)
#pragma unroll
        for (int j = 0; j < 4; j++)
#pragma unroll
            for (int q = 0; q < 4; q++) { cg[i][j][q] = 0.f; cu[i][j][q] = 0.f; }

    int ar = tid >> 1, ac = (tid & 1) * 8;
    int bk = tid >> 4, bn = (tid & 15) * 4;

    const float* a_base = A + (size_t)(row0 + ar) * HD + ac;

    cp16(&As[0][ar][ac],     a_base);
    cp16(&As[0][ar][ac + 4], a_base + 4);
    {
        const float* bsrc = B + (size_t)bk * TWO_I + col0 + bn;
        cp16(&Bg[0][bk][bn], bsrc);
        cp16(&Bu[0][bk][bn], bsrc + ID);
    }
    cp_commit();

    const int NIT = HD / 16;
    for (int it = 0; it < NIT; it++) {
        int nxt = (it + 1) & 1, cur = it & 1;
        if (it + 1 < NIT) {
            int k0 = (it + 1) * 16;
            cp16(&As[nxt][ar][ac],     a_base + k0);
            cp16(&As[nxt][ar][ac + 4], a_base + k0 + 4);
            const float* bsrc = B + (size_t)(k0 + bk) * TWO_I + col0 + bn;
            cp16(&Bg[nxt][bk][bn], bsrc);
            cp16(&Bu[nxt][bk][bn], bsrc + ID);
        }
        cp_commit();
        cp_wait1();
        __syncthreads();

#pragma unroll
        for (int ks = 0; ks < 2; ks++) {
            int kb = ks * 8;
            float a[2][4];
#pragma unroll
            for (int mt = 0; mt < 2; mt++) {
                int r = wm * 32 + mt * 16 + (lane >> 2);
                int c = kb + (lane & 3);
                a[mt][0] = As[cur][r][c];
                a[mt][1] = As[cur][r + 8][c];
                a[mt][2] = As[cur][r][c + 4];
                a[mt][3] = As[cur][r + 8][c + 4];
            }
#pragma unroll
            for (int nt = 0; nt < 4; nt++) {
                int n = wn * 32 + nt * 8 + (lane >> 2);
                int c = kb + (lane & 3);
                float bg0 = Bg[cur][c][n], bg1 = Bg[cur][c + 4][n];
                float bu0 = Bu[cur][c][n], bu1 = Bu[cur][c + 4][n];
#pragma unroll
                for (int mt = 0; mt < 2; mt++) {
                    mma_tf32(cg[mt][nt], a[mt], bg0, bg1);
                    mma_tf32(cu[mt][nt], a[mt], bu0, bu1);
                }
            }
        }
        __syncthreads();
    }

#pragma unroll
    for (int mt = 0; mt < 2; mt++) {
#pragma unroll
        for (int nt = 0; nt < 4; nt++) {
            int rb = row0 + wm * 32 + mt * 16 + (lane >> 2);
            int nb = col0 + wn * 32 + nt * 8 + (lane & 3) * 2;
#pragma unroll
            for (int q = 0; q < 4; q++) {
                int rr = rb + ((q >= 2) ? 8 : 0);
                int nn = nb + (q & 1);
                float g = cg[mt][nt][q], u = cu[mt][nt][q];
                float s = 1.f / (1.f + __expf(-g));
                Hout[(size_t)rr * ID + nn] = to_tf32(g * s * u);
            }
        }
    }
}

// ---------------- GEMM2: hidden @ W_down, cp.async 2-stage, atomic epilogue ----------------
#define BS_STR 136
__global__ __launch_bounds__(256, 2) void gemm2_kernel(const float* __restrict__ wd,
                                                       const float* __restrict__ wsd,
                                                       float* __restrict__ out) {
    int bx = blockIdx.x;
    bool sh = (bx >= RT_TILES);
    int row0, vrows;
    const float* A;
    const float* B;
    if (sh) {
        row0 = (bx - RT_TILES) * 128; vrows = 128;
        A = g_shidden; B = wsd;
    } else {
        if (bx >= g_ntiles) return;
        row0 = g_tile_row0[bx];
        vrows = g_tile_rows[bx];
        A = g_hidden;
        B = wd + (size_t)g_tile_e[bx] * ID * HD;
    }
    int col0 = blockIdx.y * 128;

    __shared__ float As[2][128][AS_STR];
    __shared__ float Bs[2][16][BS_STR];

    int tid = threadIdx.x, lane = tid & 31, warp = tid >> 5;
    int wm = warp >> 1, wn = warp & 1;

    float c[2][8][4];
#pragma unroll
    for (int i = 0; i < 2; i++)
#pragma unroll
        for (int j = 0; j < 8; j++)
#pragma unroll
            for (int q = 0; q < 4; q++) c[i][j][q] = 0.f;

    int ar = tid >> 1, ac = (tid & 1) * 8;
    int bk = tid >> 4, bn = (tid & 15) * 8;

    const float* a_base = A + (size_t)(row0 + ar) * ID + ac;

    cp16(&As[0][ar][ac],     a_base);
    cp16(&As[0][ar][ac + 4], a_base + 4);
    {
        const float* bsrc = B + (size_t)bk * HD + col0 + bn;
        cp16(&Bs[0][bk][bn],     bsrc);
        cp16(&Bs[0][bk][bn + 4], bsrc + 4);
    }
    cp_commit();

    const int NIT = ID / 16;
    for (int it = 0; it < NIT; it++) {
        int nxt = (it + 1) & 1, cur = it & 1;
        if (it + 1 < NIT) {
            int k0 = (it + 1) * 16;
            cp16(&As[nxt][ar][ac],     a_base + k0);
            cp16(&As[nxt][ar][ac + 4], a_base + k0 + 4);
            const float* bsrc = B + (size_t)(k0 + bk) * HD + col0 + bn;
            cp16(&Bs[nxt][bk][bn],     bsrc);
            cp16(&Bs[nxt][bk][bn + 4], bsrc + 4);
        }
        cp_commit();
        cp_wait1();
        __syncthreads();

#pragma unroll
        for (int ks = 0; ks < 2; ks++) {
            int kb = ks * 8;
            float a[2][4];
#pragma unroll
            for (int mt = 0; mt < 2; mt++) {
                int r = wm * 32 + mt * 16 + (lane >> 2);
                int cc = kb + (lane & 3);
                a[mt][0] = As[cur][r][cc];
                a[mt][1] = As[cur][r + 8][cc];
                a[mt][2] = As[cur][r][cc + 4];
                a[mt][3] = As[cur][r + 8][cc + 4];
            }
#pragma unroll
            for (int nt = 0; nt < 8; nt++) {
                int n = wn * 64 + nt * 8 + (lane >> 2);
                int cc = kb + (lane & 3);
                float b0 = Bs[cur][cc][n];
                float b1 = Bs[cur][cc + 4][n];
#pragma unroll
                for (int mt = 0; mt < 2; mt++) mma_tf32(c[mt][nt], a[mt], b0, b1);
            }
        }
        __syncthreads();
    }

#pragma unroll
    for (int mt = 0; mt < 2; mt++) {
#pragma unroll
        for (int nt = 0; nt < 8; nt++) {
            int lr0 = wm * 32 + mt * 16 + (lane >> 2);
            int nb  = col0 + wn * 64 + nt * 8 + (lane & 3) * 2;
#pragma unroll
            for (int q = 0; q < 4; q++) {
                int lr = lr0 + ((q >= 2) ? 8 : 0);
                int nn = nb + (q & 1);
                float v = c[mt][nt][q];
                if (lr < vrows) {
                    if (sh) {
                        int t = row0 + lr;
                        atomicAdd(&out[(size_t)t * HD + nn], g_gate[t] * v);
                    } else {
                        int t = g_row_token[row0 + lr];
                        atomicAdd(&out[(size_t)t * HD + nn], v);
                    }
                }
            }
        }
    }
}

// ---------------- launch ----------------
extern "C" void kernel_launch(void* const* d_in, const int* in_sizes, int n_in,
                              void* d_out, int out_size) {
    const float* x    = (const float*)d_in[0];
    const float* wr   = (const float*)d_in[1];
    const float* wgu  = (const float*)d_in[2];
    const float* wd   = (const float*)d_in[3];
    const float* wsgu = (const float*)d_in[4];
    const float* wsd  = (const float*)d_in[5];
    const float* wsg  = (const float*)d_in[6];
    float* out = (float*)d_out;

    float* wgu_t;  cudaGetSymbolAddress((void**)&wgu_t,  g_wgu_t);
    float* wd_t;   cudaGetSymbolAddress((void**)&wd_t,   g_wd_t);
    float* wsgu_t; cudaGetSymbolAddress((void**)&wsgu_t, g_wsgu_t);
    float* wsd_t;  cudaGetSymbolAddress((void**)&wsd_t,  g_wsd_t);
    float* xt;     cudaGetSymbolAddress((void**)&xt,     g_xt);

    init_kernel<<<1, 32>>>();
    router_kernel<<<T_TOK / 8, 256>>>(x, wr, wsg);
    scan_kernel<<<1, 1>>>();
    scatter_kernel<<<NA, 256>>>(x);

    // hoisted tf32 rounding of all GEMM operands
    cvt_kernel<<<2048, 256>>>((const float4*)wgu,  (float4*)wgu_t,  NE * HD * TWO_I / 4);
    cvt_kernel<<<2048, 256>>>((const float4*)wd,   (float4*)wd_t,   NE * ID * HD / 4);
    cvt_kernel<<<1024, 256>>>((const float4*)wsgu, (float4*)wsgu_t, HD * TWO_I / 4);
    cvt_kernel<<<1024, 256>>>((const float4*)wsd,  (float4*)wsd_t,  ID * HD / 4);
    cvt_kernel<<<1024, 256>>>((const float4*)x,    (float4*)xt,     T_TOK * HD / 4);

    cudaMemsetAsync(out, 0, (size_t)out_size * sizeof(float), 0);

    gemm1_kernel<<<dim3(RT_TILES + T_TOK / 128, TWO_I / 2 / 64), 256>>>(wgu_t, wsgu_t);
    gemm2_kernel<<<dim3(RT_TILES + T_TOK / 128, HD / 128), 256>>>(wd_t, wsd_t, out);
}

// round 7
// speedup vs baseline: 1.0020x; 1.0020x over previous
#include <cuda_runtime.h>
#include <math.h>

#define T_TOK 8192
#define HD    2048
#define NE    8
#define ID    1408
#define TWO_I 2816
#define NA    16384
#define NA_PAD 17408   // 16384 + 8*128: per-expert regions aligned to 128 rows
#define MAX_TILES 144
#define RT_TILES 136   // fixed routed-tile grid slots; shared tiles start here

// ---------------- scratch (device globals; no allocation allowed) ----------------
__device__ float g_xin[(size_t)NA_PAD * HD];       // tf32(x*p), expert-grouped
__device__ float g_hidden[(size_t)NA_PAD * ID];    // tf32 routed swiglu
__device__ float g_shidden[(size_t)T_TOK * ID];    // tf32 shared swiglu
// tf32-rounded mirrors (conversion hoisted out of GEMM inner loops)
__device__ float g_xt[(size_t)T_TOK * HD];
__device__ float g_wgu_t[(size_t)NE * HD * TWO_I];
__device__ float g_wd_t[(size_t)NE * ID * HD];
__device__ float g_wsgu_t[(size_t)HD * TWO_I];
__device__ float g_wsd_t[(size_t)ID * HD];
__device__ int   g_top_e[NA];
__device__ float g_top_p[NA];
__device__ float g_gate[T_TOK];
__device__ int   g_cnt[NE], g_off[NE], g_fill[NE];
__device__ int   g_row_token[NA_PAD];
__device__ int   g_tile_e[MAX_TILES], g_tile_row0[MAX_TILES], g_tile_rows[MAX_TILES];
__device__ int   g_ntiles;

// ---------------- helpers ----------------
__device__ __forceinline__ float to_tf32(float f) {
    unsigned u;
    asm("cvt.rna.tf32.f32 %0, %1;" : "=r"(u) : "f"(f));
    return __uint_as_float(u);
}

__device__ __forceinline__ void mma_tf32(float* c, const float* a, float b0, float b1) {
    asm volatile(
        "mma.sync.aligned.m16n8k8.row.col.f32.tf32.tf32.f32 "
        "{%0,%1,%2,%3}, {%4,%5,%6,%7}, {%8,%9}, {%0,%1,%2,%3};\n"
        : "+f"(c[0]), "+f"(c[1]), "+f"(c[2]), "+f"(c[3])
        : "r"(__float_as_uint(a[0])), "r"(__float_as_uint(a[1])),
          "r"(__float_as_uint(a[2])), "r"(__float_as_uint(a[3])),
          "r"(__float_as_uint(b0)),  "r"(__float_as_uint(b1)));
}

__device__ __forceinline__ void cp16(void* dst, const void* src) {
    unsigned d = (unsigned)__cvta_generic_to_shared(dst);
    asm volatile("cp.async.cg.shared.global [%0], [%1], 16;\n" :: "r"(d), "l"(src));
}
__device__ __forceinline__ void cp_commit() { asm volatile("cp.async.commit_group;\n"); }
__device__ __forceinline__ void cp_wait1()  { asm volatile("cp.async.wait_group 1;\n"); }

// ---------------- small kernels ----------------
__global__ void init_kernel() {
    int t = threadIdx.x;
    if (t < NE) { g_cnt[t] = 0; g_fill[t] = 0; }
}

// tf32-round a tensor (vectorized grid-stride)
__global__ void cvt_kernel(const float4* __restrict__ src, float4* __restrict__ dst, int n4) {
    int i = blockIdx.x * blockDim.x + threadIdx.x;
    int stride = gridDim.x * blockDim.x;
    for (; i < n4; i += stride) {
        float4 v = src[i];
        v.x = to_tf32(v.x); v.y = to_tf32(v.y);
        v.z = to_tf32(v.z); v.w = to_tf32(v.w);
        dst[i] = v;
    }
}

__global__ void router_kernel(const float* __restrict__ x,
                              const float* __restrict__ wr,
                              const float* __restrict__ wsg) {
    int gw   = (blockIdx.x * blockDim.x + threadIdx.x) >> 5;
    int lane = threadIdx.x & 31;
    if (gw >= T_TOK) return;
    const float* xr = x + (size_t)gw * HD;
    float acc[NE];
#pragma unroll
    for (int e = 0; e < NE; e++) acc[e] = 0.f;
    float ag = 0.f;
    for (int h = lane; h < HD; h += 32) {
        float xv = xr[h];
        const float4* w = (const float4*)(wr + (size_t)h * NE);
        float4 w0 = w[0], w1 = w[1];
        acc[0] += xv * w0.x; acc[1] += xv * w0.y; acc[2] += xv * w0.z; acc[3] += xv * w0.w;
        acc[4] += xv * w1.x; acc[5] += xv * w1.y; acc[6] += xv * w1.z; acc[7] += xv * w1.w;
        ag += xv * wsg[h];
    }
#pragma unroll
    for (int o = 16; o > 0; o >>= 1) {
#pragma unroll
        for (int e = 0; e < NE; e++) acc[e] += __shfl_xor_sync(0xffffffffu, acc[e], o);
        ag += __shfl_xor_sync(0xffffffffu, ag, o);
    }
    if (lane == 0) {
        int i0 = 0; float v0 = acc[0];
#pragma unroll
        for (int e = 1; e < NE; e++) if (acc[e] > v0) { v0 = acc[e]; i0 = e; }
        int i1 = -1; float v1 = -1e30f;
#pragma unroll
        for (int e = 0; e < NE; e++) if (e != i0 && acc[e] > v1) { v1 = acc[e]; i1 = e; }
        float t  = __expf(v1 - v0);
        float p0 = 1.f / (1.f + t);
        float p1 = t  / (1.f + t);
        g_top_e[gw * 2]     = i0;
        g_top_e[gw * 2 + 1] = i1;
        g_top_p[gw * 2]     = p0;
        g_top_p[gw * 2 + 1] = p1;
        atomicAdd(&g_cnt[i0], 1);
        atomicAdd(&g_cnt[i1], 1);
        g_gate[gw] = 1.f / (1.f + __expf(-ag));
    }
}

// Expert regions aligned UP to 128 so no tile straddles two experts (R4 fix).
__global__ void scan_kernel() {
    if (threadIdx.x == 0 && blockIdx.x == 0) {
        int off = 0, nt = 0;
        for (int e = 0; e < NE; e++) {
            g_off[e] = off;
            int c = g_cnt[e];
            for (int r = 0; r < c; r += 128) {
                g_tile_e[nt]    = e;
                g_tile_row0[nt] = off + r;
                g_tile_rows[nt] = (c - r < 128) ? (c - r) : 128;
                nt++;
            }
            off = (off + c + 127) & ~127;
        }
        g_ntiles = nt;
    }
}

// copy tf32(x[t]*p) into the expert-grouped buffer
__global__ void scatter_kernel(const float* __restrict__ x) {
    int a = blockIdx.x;
    int t = a >> 1;
    __shared__ int srow;
    int   e = g_top_e[a];
    float p = g_top_p[a];
    if (threadIdx.x == 0) {
        int pos = atomicAdd(&g_fill[e], 1);
        int row = g_off[e] + pos;
        g_row_token[row] = t;
        srow = row;
    }
    __syncthreads();
    int row = srow;
    const float4* src = (const float4*)(x + (size_t)t * HD);
    float4*       dst = (float4*)(g_xin + (size_t)row * HD);
    for (int i = threadIdx.x; i < HD / 4; i += blockDim.x) {
        float4 v = src[i];
        v.x = to_tf32(v.x * p); v.y = to_tf32(v.y * p);
        v.z = to_tf32(v.z * p); v.w = to_tf32(v.w * p);
        dst[i] = v;
    }
}

// ---------------- GEMM1: X @ W_gate_up, fused SwiGLU, cp.async 2-stage ----------------
// All operands pre-rounded to tf32 — inner loop is pure LDS+MMA.
#define AS_STR 20
#define BG_STR 72
__global__ __launch_bounds__(256, 2) void gemm1_kernel(const float* __restrict__ wgu,
                                                       const float* __restrict__ wsgu) {
    int bx = blockIdx.x;
    bool sh = (bx >= RT_TILES);
    int row0;
    const float* A;
    const float* B;
    float* Hout;
    if (sh) {
        row0 = (bx - RT_TILES) * 128;
        A = g_xt; B = wsgu; Hout = g_shidden;
    } else {
        if (bx >= g_ntiles) return;
        row0 = g_tile_row0[bx];
        A = g_xin;
        B = wgu + (size_t)g_tile_e[bx] * HD * TWO_I;
        Hout = g_hidden;
    }
    int col0 = blockIdx.y * 64;

    __shared__ float As[2][128][AS_STR];
    __shared__ float Bg[2][16][BG_STR];
    __shared__ float Bu[2][16][BG_STR];

    int tid = threadIdx.x, lane = tid & 31, warp = tid >> 5;
    int wm = warp >> 1, wn = warp & 1;

    float cg[2][4][4], cu[2][4][4];
#pragma unroll
    for (int i = 0; i < 2; i++)
#pragma unroll
        for (int j = 0; j < 4; j++)
#pragma unroll
            for (int q = 0; q < 4; q++) { cg[i][j][q] = 0.f; cu[i][j][q] = 0.f; }

    int ar = tid >> 1, ac = (tid & 1) * 8;
    int bk = tid >> 4, bn = (tid & 15) * 4;

    const float* a_base = A + (size_t)(row0 + ar) * HD + ac;

    cp16(&As[0][ar][ac],     a_base);
    cp16(&As[0][ar][ac + 4], a_base + 4);
    {
        const float* bsrc = B + (size_t)bk * TWO_I + col0 + bn;
        cp16(&Bg[0][bk][bn], bsrc);
        cp16(&Bu[0][bk][bn], bsrc + ID);
    }
    cp_commit();

    const int NIT = HD / 16;
    for (int it = 0; it < NIT; it++) {
        int nxt = (it + 1) & 1, cur = it & 1;
        if (it + 1 < NIT) {
            int k0 = (it + 1) * 16;
            cp16(&As[nxt][ar][ac],     a_base + k0);
            cp16(&As[nxt][ar][ac + 4], a_base + k0 + 4);
            const float* bsrc = B + (size_t)(k0 + bk) * TWO_I + col0 + bn;
            cp16(&Bg[nxt][bk][bn], bsrc);
            cp16(&Bu[nxt][bk][bn], bsrc + ID);
        }
        cp_commit();
        cp_wait1();
        __syncthreads();

#pragma unroll
        for (int ks = 0; ks < 2; ks++) {
            int kb = ks * 8;
            float a[2][4];
#pragma unroll
            for (int mt = 0; mt < 2; mt++) {
                int r = wm * 32 + mt * 16 + (lane >> 2);
                int c = kb + (lane & 3);
                a[mt][0] = As[cur][r][c];
                a[mt][1] = As[cur][r + 8][c];
                a[mt][2] = As[cur][r][c + 4];
                a[mt][3] = As[cur][r + 8][c + 4];
            }
#pragma unroll
            for (int nt = 0; nt < 4; nt++) {
                int n = wn * 32 + nt * 8 + (lane >> 2);
                int c = kb + (lane & 3);
                float bg0 = Bg[cur][c][n], bg1 = Bg[cur][c + 4][n];
                float bu0 = Bu[cur][c][n], bu1 = Bu[cur][c + 4][n];
#pragma unroll
                for (int mt = 0; mt < 2; mt++) {
                    mma_tf32(cg[mt][nt], a[mt], bg0, bg1);
                    mma_tf32(cu[mt][nt], a[mt], bu0, bu1);
                }
            }
        }
        __syncthreads();
    }

#pragma unroll
    for (int mt = 0; mt < 2; mt++) {
#pragma unroll
        for (int nt = 0; nt < 4; nt++) {
            int rb = row0 + wm * 32 + mt * 16 + (lane >> 2);
            int nb = col0 + wn * 32 + nt * 8 + (lane & 3) * 2;
#pragma unroll
            for (int q = 0; q < 4; q++) {
                int rr = rb + ((q >= 2) ? 8 : 0);
                int nn = nb + (q & 1);
                float g = cg[mt][nt][q], u = cu[mt][nt][q];
                float s = 1.f / (1.f + __expf(-g));
                Hout[(size_t)rr * ID + nn] = to_tf32(g * s * u);
            }
        }
    }
}

// ---------------- GEMM2: hidden @ W_down, cp.async 2-stage, atomic epilogue ----------------
#define BS_STR 136
__global__ __launch_bounds__(256, 2) void gemm2_kernel(const float* __restrict__ wd,
                                                       const float* __restrict__ wsd,
                                                       float* __restrict__ out) {
    int bx = blockIdx.x;
    bool sh = (bx >= RT_TILES);
    int row0, vrows;
    const float* A;
    const float* B;
    if (sh) {
        row0 = (bx - RT_TILES) * 128; vrows = 128;
        A = g_shidden; B = wsd;
    } else {
        if (bx >= g_ntiles) return;
        row0 = g_tile_row0[bx];
        vrows = g_tile_rows[bx];
        A = g_hidden;
        B = wd + (size_t)g_tile_e[bx] * ID * HD;
    }
    int col0 = blockIdx.y * 128;

    __shared__ float As[2][128][AS_STR];
    __shared__ float Bs[2][16][BS_STR];

    int tid = threadIdx.x, lane = tid & 31, warp = tid >> 5;
    int wm = warp >> 1, wn = warp & 1;

    float c[2][8][4];
#pragma unroll
    for (int i = 0; i < 2; i++)
#pragma unroll
        for (int j = 0; j < 8; j++)
#pragma unroll
            for (int q = 0; q < 4; q++) c[i][j][q] = 0.f;

    int ar = tid >> 1, ac = (tid & 1) * 8;
    int bk = tid >> 4, bn = (tid & 15) * 8;

    const float* a_base = A + (size_t)(row0 + ar) * ID + ac;

    cp16(&As[0][ar][ac],     a_base);
    cp16(&As[0][ar][ac + 4], a_base + 4);
    {
        const float* bsrc = B + (size_t)bk * HD + col0 + bn;
        cp16(&Bs[0][bk][bn],     bsrc);
        cp16(&Bs[0][bk][bn + 4], bsrc + 4);
    }
    cp_commit();

    const int NIT = ID / 16;
    for (int it = 0; it < NIT; it++) {
        int nxt = (it + 1) & 1, cur = it & 1;
        if (it + 1 < NIT) {
            int k0 = (it + 1) * 16;
            cp16(&As[nxt][ar][ac],     a_base + k0);
            cp16(&As[nxt][ar][ac + 4], a_base + k0 + 4);
            const float* bsrc = B + (size_t)(k0 + bk) * HD + col0 + bn;
            cp16(&Bs[nxt][bk][bn],     bsrc);
            cp16(&Bs[nxt][bk][bn + 4], bsrc + 4);
        }
        cp_commit();
        cp_wait1();
        __syncthreads();

#pragma unroll
        for (int ks = 0; ks < 2; ks++) {
            int kb = ks * 8;
            float a[2][4];
#pragma unroll
            for (int mt = 0; mt < 2; mt++) {
                int r = wm * 32 + mt * 16 + (lane >> 2);
                int cc = kb + (lane & 3);
                a[mt][0] = As[cur][r][cc];
                a[mt][1] = As[cur][r + 8][cc];
                a[mt][2] = As[cur][r][cc + 4];
                a[mt][3] = As[cur][r + 8][cc + 4];
            }
#pragma unroll
            for (int nt = 0; nt < 8; nt++) {
                int n = wn * 64 + nt * 8 + (lane >> 2);
                int cc = kb + (lane & 3);
                float b0 = Bs[cur][cc][n];
                float b1 = Bs[cur][cc + 4][n];
#pragma unroll
                for (int mt = 0; mt < 2; mt++) mma_tf32(c[mt][nt], a[mt], b0, b1);
            }
        }
        __syncthreads();
    }

#pragma unroll
    for (int mt = 0; mt < 2; mt++) {
#pragma unroll
        for (int nt = 0; nt < 8; nt++) {
            int lr0 = wm * 32 + mt * 16 + (lane >> 2);
            int nb  = col0 + wn * 64 + nt * 8 + (lane & 3) * 2;
#pragma unroll
            for (int q = 0; q < 4; q++) {
                int lr = lr0 + ((q >= 2) ? 8 : 0);
                int nn = nb + (q & 1);
                float v = c[mt][nt][q];
                if (lr < vrows) {
                    if (sh) {
                        int t = row0 + lr;
                        atomicAdd(&out[(size_t)t * HD + nn], g_gate[t] * v);
                    } else {
                        int t = g_row_token[row0 + lr];
                        atomicAdd(&out[(size_t)t * HD + nn], v);
                    }
                }
            }
        }
    }
}

// ---------------- launch ----------------
extern "C" void kernel_launch(void* const* d_in, const int* in_sizes, int n_in,
                              void* d_out, int out_size) {
    const float* x    = (const float*)d_in[0];
    const float* wr   = (const float*)d_in[1];
    const float* wgu  = (const float*)d_in[2];
    const float* wd   = (const float*)d_in[3];
    const float* wsgu = (const float*)d_in[4];
    const float* wsd  = (const float*)d_in[5];
    const float* wsg  = (const float*)d_in[6];
    float* out = (float*)d_out;

    float* wgu_t;  cudaGetSymbolAddress((void**)&wgu_t,  g_wgu_t);
    float* wd_t;   cudaGetSymbolAddress((void**)&wd_t,   g_wd_t);
    float* wsgu_t; cudaGetSymbolAddress((void**)&wsgu_t, g_wsgu_t);
    float* wsd_t;  cudaGetSymbolAddress((void**)&wsd_t,  g_wsd_t);
    float* xt;     cudaGetSymbolAddress((void**)&xt,     g_xt);

    init_kernel<<<1, 32>>>();
    router_kernel<<<T_TOK / 8, 256>>>(x, wr, wsg);
    scan_kernel<<<1, 1>>>();
    scatter_kernel<<<NA, 256>>>(x);

    // hoisted tf32 rounding of all GEMM operands
    cvt_kernel<<<2048, 256>>>((const float4*)wgu,  (float4*)wgu_t,  NE * HD * TWO_I / 4);
    cvt_kernel<<<2048, 256>>>((const float4*)wd,   (float4*)wd_t,   NE * ID * HD / 4);
    cvt_kernel<<<1024, 256>>>((const float4*)wsgu, (float4*)wsgu_t, HD * TWO_I / 4);
    cvt_kernel<<<1024, 256>>>((const float4*)wsd,  (float4*)wsd_t,  ID * HD / 4);
    cvt_kernel<<<1024, 256>>>((const float4*)x,    (float4*)xt,     T_TOK * HD / 4);

    cudaMemsetAsync(out, 0, (size_t)out_size * sizeof(float), 0);

    gemm1_kernel<<<dim3(RT_TILES + T_TOK / 128, TWO_I / 2 / 64), 256>>>(wgu_t, wsgu_t);
    gemm2_kernel<<<dim3(RT_TILES + T_TOK / 128, HD / 128), 256>>>(wd_t, wsd_t, out);
}

// round 8
// speedup vs baseline: 1.0560x; 1.0538x over previous
#include <cuda_runtime.h>
#include <math.h>

#define T_TOK 8192
#define HD    2048
#define NE    8
#define ID    1408
#define TWO_I 2816
#define NA    16384
#define NA_PAD 17408   // 16384 + 8*128: per-expert regions aligned to 128 rows
#define MAX_TILES 144
#define RT_TILES 136   // fixed routed-tile grid slots; shared tiles start here

// ---------------- scratch (device globals; no allocation allowed) ----------------
__device__ float g_xin[(size_t)NA_PAD * HD];
__device__ float g_hidden[(size_t)NA_PAD * ID];
__device__ float g_shidden[(size_t)T_TOK * ID];
__device__ int   g_top_e[NA];
__device__ float g_top_p[NA];
__device__ float g_gate[T_TOK];
__device__ int   g_cnt[NE], g_off[NE], g_fill[NE];
__device__ int   g_row_token[NA_PAD];
__device__ int   g_tile_e[MAX_TILES], g_tile_row0[MAX_TILES], g_tile_rows[MAX_TILES];
__device__ int   g_ntiles;

// ---------------- helpers ----------------
__device__ __forceinline__ float to_tf32(float f) {
    unsigned u;
    asm("cvt.rna.tf32.f32 %0, %1;" : "=r"(u) : "f"(f));
    return __uint_as_float(u);
}

__device__ __forceinline__ void mma_tf32(float* c, const float* a, float b0, float b1) {
    asm volatile(
        "mma.sync.aligned.m16n8k8.row.col.f32.tf32.tf32.f32 "
        "{%0,%1,%2,%3}, {%4,%5,%6,%7}, {%8,%9}, {%0,%1,%2,%3};\n"
        : "+f"(c[0]), "+f"(c[1]), "+f"(c[2]), "+f"(c[3])
        : "r"(__float_as_uint(a[0])), "r"(__float_as_uint(a[1])),
          "r"(__float_as_uint(a[2])), "r"(__float_as_uint(a[3])),
          "r"(__float_as_uint(b0)),  "r"(__float_as_uint(b1)));
}

__device__ __forceinline__ void cp16(void* dst, const void* src) {
    unsigned d = (unsigned)__cvta_generic_to_shared(dst);
    asm volatile("cp.async.cg.shared.global [%0], [%1], 16;\n" :: "r"(d), "l"(src));
}
__device__ __forceinline__ void cp_commit() { asm volatile("cp.async.commit_group;\n"); }
__device__ __forceinline__ void cp_wait1()  { asm volatile("cp.async.wait_group 1;\n"); }

// ---------------- small kernels ----------------
__global__ void init_kernel() {
    int t = threadIdx.x;
    if (t < NE) { g_cnt[t] = 0; g_fill[t] = 0; }
}

__global__ void router_kernel(const float* __restrict__ x,
                              const float* __restrict__ wr,
                              const float* __restrict__ wsg) {
    int gw   = (blockIdx.x * blockDim.x + threadIdx.x) >> 5;
    int lane = threadIdx.x & 31;
    if (gw >= T_TOK) return;
    const float* xr = x + (size_t)gw * HD;
    float acc[NE];
#pragma unroll
    for (int e = 0; e < NE; e++) acc[e] = 0.f;
    float ag = 0.f;
    for (int h = lane; h < HD; h += 32) {
        float xv = xr[h];
        const float4* w = (const float4*)(wr + (size_t)h * NE);
        float4 w0 = w[0], w1 = w[1];
        acc[0] += xv * w0.x; acc[1] += xv * w0.y; acc[2] += xv * w0.z; acc[3] += xv * w0.w;
        acc[4] += xv * w1.x; acc[5] += xv * w1.y; acc[6] += xv * w1.z; acc[7] += xv * w1.w;
        ag += xv * wsg[h];
    }
#pragma unroll
    for (int o = 16; o > 0; o >>= 1) {
#pragma unroll
        for (int e = 0; e < NE; e++) acc[e] += __shfl_xor_sync(0xffffffffu, acc[e], o);
        ag += __shfl_xor_sync(0xffffffffu, ag, o);
    }
    if (lane == 0) {
        int i0 = 0; float v0 = acc[0];
#pragma unroll
        for (int e = 1; e < NE; e++) if (acc[e] > v0) { v0 = acc[e]; i0 = e; }
        int i1 = -1; float v1 = -1e30f;
#pragma unroll
        for (int e = 0; e < NE; e++) if (e != i0 && acc[e] > v1) { v1 = acc[e]; i1 = e; }
        float t  = __expf(v1 - v0);
        float p0 = 1.f / (1.f + t);
        float p1 = t  / (1.f + t);
        g_top_e[gw * 2]     = i0;
        g_top_e[gw * 2 + 1] = i1;
        g_top_p[gw * 2]     = p0;
        g_top_p[gw * 2 + 1] = p1;
        atomicAdd(&g_cnt[i0], 1);
        atomicAdd(&g_cnt[i1], 1);
        g_gate[gw] = 1.f / (1.f + __expf(-ag));
    }
}

// Expert regions aligned UP to 128 so no tile straddles two experts (R4 fix).
__global__ void scan_kernel() {
    if (threadIdx.x == 0 && blockIdx.x == 0) {
        int off = 0, nt = 0;
        for (int e = 0; e < NE; e++) {
            g_off[e] = off;
            int c = g_cnt[e];
            for (int r = 0; r < c; r += 128) {
                g_tile_e[nt]    = e;
                g_tile_row0[nt] = off + r;
                g_tile_rows[nt] = (c - r < 128) ? (c - r) : 128;
                nt++;
            }
            off = (off + c + 127) & ~127;
        }
        g_ntiles = nt;
    }
}

__global__ void scatter_kernel(const float* __restrict__ x) {
    int a = blockIdx.x;
    int t = a >> 1;
    __shared__ int srow;
    int   e = g_top_e[a];
    float p = g_top_p[a];
    if (threadIdx.x == 0) {
        int pos = atomicAdd(&g_fill[e], 1);
        int row = g_off[e] + pos;
        g_row_token[row] = t;
        srow = row;
    }
    __syncthreads();
    int row = srow;
    const float4* src = (const float4*)(x + (size_t)t * HD);
    float4*       dst = (float4*)(g_xin + (size_t)row * HD);
    for (int i = threadIdx.x; i < HD / 4; i += blockDim.x) {
        float4 v = src[i];
        v.x *= p; v.y *= p; v.z *= p; v.w *= p;
        dst[i] = v;
    }
}

// ---------------- GEMM1: X @ W_gate_up, fused SwiGLU, cp.async 2-stage ----------------
// Grid axes SWAPPED vs R5: blockIdx.x = column block (fastest) so a scheduling
// wave covers all 22 col-blocks of ~13 row-tiles -> A tile DRAM-read once, then
// L2-hit 21x. blockIdx.y = row tile (routed [0,136) + shared [136,200)).
#define AS_STR 20
#define BG_STR 72
__global__ __launch_bounds__(256, 2) void gemm1_kernel(const float* __restrict__ xglob,
                                                       const float* __restrict__ wgu,
                                                       const float* __restrict__ wsgu) {
    int bx = blockIdx.y;                       // row tile
    bool sh = (bx >= RT_TILES);
    int row0;
    const float* A;
    const float* B;
    float* Hout;
    if (sh) {
        row0 = (bx - RT_TILES) * 128;
        A = xglob; B = wsgu; Hout = g_shidden;
    } else {
        if (bx >= g_ntiles) return;
        row0 = g_tile_row0[bx];
        A = g_xin;
        B = wgu + (size_t)g_tile_e[bx] * HD * TWO_I;
        Hout = g_hidden;
    }
    int col0 = blockIdx.x * 64;                // column block (fastest axis)

    __shared__ float As[2][128][AS_STR];
    __shared__ float Bg[2][16][BG_STR];
    __shared__ float Bu[2][16][BG_STR];

    int tid = threadIdx.x, lane = tid & 31, warp = tid >> 5;
    int wm = warp >> 1, wn = warp & 1;

    float cg[2][4][4], cu[2][4][4];
#pragma unroll
    for (int i = 0; i < 2; i++)
#pragma unroll
        for (int j = 0; j < 4; j++)
#pragma unroll
            for (int q = 0; q < 4; q++) { cg[i][j][q] = 0.f; cu[i][j][q] = 0.f; }

    int ar = tid >> 1, ac = (tid & 1) * 8;
    int bk = tid >> 4, bn = (tid & 15) * 4;

    const float* a_base = A + (size_t)(row0 + ar) * HD + ac;

    cp16(&As[0][ar][ac],     a_base);
    cp16(&As[0][ar][ac + 4], a_base + 4);
    {
        const float* bsrc = B + (size_t)bk * TWO_I + col0 + bn;
        cp16(&Bg[0][bk][bn], bsrc);
        cp16(&Bu[0][bk][bn], bsrc + ID);
    }
    cp_commit();

    const int NIT = HD / 16;
    for (int it = 0; it < NIT; it++) {
        int nxt = (it + 1) & 1, cur = it & 1;
        if (it + 1 < NIT) {
            int k0 = (it + 1) * 16;
            cp16(&As[nxt][ar][ac],     a_base + k0);
            cp16(&As[nxt][ar][ac + 4], a_base + k0 + 4);
            const float* bsrc = B + (size_t)(k0 + bk) * TWO_I + col0 + bn;
            cp16(&Bg[nxt][bk][bn], bsrc);
            cp16(&Bu[nxt][bk][bn], bsrc + ID);
        }
        cp_commit();
        cp_wait1();
        __syncthreads();

#pragma unroll
        for (int ks = 0; ks < 2; ks++) {
            int kb = ks * 8;
            float a[2][4];
#pragma unroll
            for (int mt = 0; mt < 2; mt++) {
                int r = wm * 32 + mt * 16 + (lane >> 2);
                int c = kb + (lane & 3);
                a[mt][0] = to_tf32(As[cur][r][c]);
                a[mt][1] = to_tf32(As[cur][r + 8][c]);
                a[mt][2] = to_tf32(As[cur][r][c + 4]);
                a[mt][3] = to_tf32(As[cur][r + 8][c + 4]);
            }
#pragma unroll
            for (int nt = 0; nt < 4; nt++) {
                int n = wn * 32 + nt * 8 + (lane >> 2);
                int c = kb + (lane & 3);
                float bg0 = to_tf32(Bg[cur][c][n]),     bg1 = to_tf32(Bg[cur][c + 4][n]);
                float bu0 = to_tf32(Bu[cur][c][n]),     bu1 = to_tf32(Bu[cur][c + 4][n]);
#pragma unroll
                for (int mt = 0; mt < 2; mt++) {
                    mma_tf32(cg[mt][nt], a[mt], bg0, bg1);
                    mma_tf32(cu[mt][nt], a[mt], bu0, bu1);
                }
            }
        }
        __syncthreads();
    }

#pragma unroll
    for (int mt = 0; mt < 2; mt++) {
#pragma unroll
        for (int nt = 0; nt < 4; nt++) {
            int rb = row0 + wm * 32 + mt * 16 + (lane >> 2);
            int nb = col0 + wn * 32 + nt * 8 + (lane & 3) * 2;
#pragma unroll
            for (int q = 0; q < 4; q++) {
                int rr = rb + ((q >= 2) ? 8 : 0);
                int nn = nb + (q & 1);
                float g = cg[mt][nt][q], u = cu[mt][nt][q];
                float s = 1.f / (1.f + __expf(-g));
                Hout[(size_t)rr * ID + nn] = g * s * u;
            }
        }
    }
}

// ---------------- GEMM2: hidden @ W_down, cp.async 2-stage, atomic epilogue ----------------
// Same grid-axis swap: blockIdx.x = column block (16), blockIdx.y = row tile (200).
#define BS_STR 136
__global__ __launch_bounds__(256, 2) void gemm2_kernel(const float* __restrict__ wd,
                                                       const float* __restrict__ wsd,
                                                       float* __restrict__ out) {
    int bx = blockIdx.y;
    bool sh = (bx >= RT_TILES);
    int row0, vrows;
    const float* A;
    const float* B;
    if (sh) {
        row0 = (bx - RT_TILES) * 128; vrows = 128;
        A = g_shidden; B = wsd;
    } else {
        if (bx >= g_ntiles) return;
        row0 = g_tile_row0[bx];
        vrows = g_tile_rows[bx];
        A = g_hidden;
        B = wd + (size_t)g_tile_e[bx] * ID * HD;
    }
    int col0 = blockIdx.x * 128;

    __shared__ float As[2][128][AS_STR];
    __shared__ float Bs[2][16][BS_STR];

    int tid = threadIdx.x, lane = tid & 31, warp = tid >> 5;
    int wm = warp >> 1, wn = warp & 1;

    float c[2][8][4];
#pragma unroll
    for (int i = 0; i < 2; i++)
#pragma unroll
        for (int j = 0; j < 8; j++)
#pragma unroll
            for (int q = 0; q < 4; q++) c[i][j][q] = 0.f;

    int ar = tid >> 1, ac = (tid & 1) * 8;
    int bk = tid >> 4, bn = (tid & 15) * 8;

    const float* a_base = A + (size_t)(row0 + ar) * ID + ac;

    cp16(&As[0][ar][ac],     a_base);
    cp16(&As[0][ar][ac + 4], a_base + 4);
    {
        const float* bsrc = B + (size_t)bk * HD + col0 + bn;
        cp16(&Bs[0][bk][bn],     bsrc);
        cp16(&Bs[0][bk][bn + 4], bsrc + 4);
    }
    cp_commit();

    const int NIT = ID / 16;
    for (int it = 0; it < NIT; it++) {
        int nxt = (it + 1) & 1, cur = it & 1;
        if (it + 1 < NIT) {
            int k0 = (it + 1) * 16;
            cp16(&As[nxt][ar][ac],     a_base + k0);
            cp16(&As[nxt][ar][ac + 4], a_base + k0 + 4);
            const float* bsrc = B + (size_t)(k0 + bk) * HD + col0 + bn;
            cp16(&Bs[nxt][bk][bn],     bsrc);
            cp16(&Bs[nxt][bk][bn + 4], bsrc + 4);
        }
        cp_commit();
        cp_wait1();
        __syncthreads();

#pragma unroll
        for (int ks = 0; ks < 2; ks++) {
            int kb = ks * 8;
            float a[2][4];
#pragma unroll
            for (int mt = 0; mt < 2; mt++) {
                int r = wm * 32 + mt * 16 + (lane >> 2);
                int cc = kb + (lane & 3);
                a[mt][0] = to_tf32(As[cur][r][cc]);
                a[mt][1] = to_tf32(As[cur][r + 8][cc]);
                a[mt][2] = to_tf32(As[cur][r][cc + 4]);
                a[mt][3] = to_tf32(As[cur][r + 8][cc + 4]);
            }
#pragma unroll
            for (int nt = 0; nt < 8; nt++) {
                int n = wn * 64 + nt * 8 + (lane >> 2);
                int cc = kb + (lane & 3);
                float b0 = to_tf32(Bs[cur][cc][n]);
                float b1 = to_tf32(Bs[cur][cc + 4][n]);
#pragma unroll
                for (int mt = 0; mt < 2; mt++) mma_tf32(c[mt][nt], a[mt], b0, b1);
            }
        }
        __syncthreads();
    }

#pragma unroll
    for (int mt = 0; mt < 2; mt++) {
#pragma unroll
        for (int nt = 0; nt < 8; nt++) {
            int lr0 = wm * 32 + mt * 16 + (lane >> 2);
            int nb  = col0 + wn * 64 + nt * 8 + (lane & 3) * 2;
#pragma unroll
            for (int q = 0; q < 4; q++) {
                int lr = lr0 + ((q >= 2) ? 8 : 0);
                int nn = nb + (q & 1);
                float v = c[mt][nt][q];
                if (lr < vrows) {
                    if (sh) {
                        int t = row0 + lr;
                        atomicAdd(&out[(size_t)t * HD + nn], g_gate[t] * v);
                    } else {
                        int t = g_row_token[row0 + lr];
                        atomicAdd(&out[(size_t)t * HD + nn], v);
                    }
                }
            }
        }
    }
}

// ---------------- launch ----------------
extern "C" void kernel_launch(void* const* d_in, const int* in_sizes, int n_in,
                              void* d_out, int out_size) {
    const float* x    = (const float*)d_in[0];
    const float* wr   = (const float*)d_in[1];
    const float* wgu  = (const float*)d_in[2];
    const float* wd   = (const float*)d_in[3];
    const float* wsgu = (const float*)d_in[4];
    const float* wsd  = (const float*)d_in[5];
    const float* wsg  = (const float*)d_in[6];
    float* out = (float*)d_out;

    init_kernel<<<1, 32>>>();
    router_kernel<<<T_TOK / 8, 256>>>(x, wr, wsg);
    scan_kernel<<<1, 1>>>();
    scatter_kernel<<<NA, 256>>>(x);
    cudaMemsetAsync(out, 0, (size_t)out_size * sizeof(float), 0);

    // grids: x = column block (fast axis -> L2 reuse of A tiles), y = row tile
    gemm1_kernel<<<dim3(TWO_I / 2 / 64, RT_TILES + T_TOK / 128), 256>>>(x, wgu, wsgu);
    gemm2_kernel<<<dim3(HD / 128, RT_TILES + T_TOK / 128), 256>>>(wd, wsd, out);
}

// round 12
// speedup vs baseline: 1.5646x; 1.4817x over previous
#include <cuda_runtime.h>
#include <cuda_fp16.h>
#include <math.h>

#define T_TOK 8192
#define HD    2048
#define NE    8
#define ID    1408
#define TWO_I 2816
#define NA    16384
#define NA_PAD 17408   // expert regions 128-aligned (R4 fix)
#define MAX_TILES 144
#define RT_TILES 136
#define STR 24         // smem row stride in halves (48B) -> conflict-free fragments

// ---------------- scratch ----------------
__device__ __half g_xin[(size_t)NA_PAD * HD];      // fp16(x*p), expert-grouped
__device__ __half g_hidden[(size_t)NA_PAD * ID];   // fp16 routed swiglu
__device__ __half g_shidden[(size_t)T_TOK * ID];   // fp16 shared swiglu
__device__ __half g_xh[(size_t)T_TOK * HD];        // fp16(x)
__device__ __half g_wgu_h[(size_t)NE * TWO_I * HD]; // [e][n][k]
__device__ __half g_wd_h[(size_t)NE * HD * ID];     // [e][n][k]
__device__ __half g_wsgu_h[(size_t)TWO_I * HD];
__device__ __half g_wsd_h[(size_t)HD * ID];
__device__ int   g_top_e[NA];
__device__ float g_top_p[NA];
__device__ float g_gate[T_TOK];
__device__ int   g_cnt[NE], g_off[NE], g_fill[NE];
__device__ int   g_row_token[NA_PAD];
__device__ int   g_tile_e[MAX_TILES], g_tile_row0[MAX_TILES], g_tile_rows[MAX_TILES];
__device__ int   g_ntiles;

// ---------------- helpers ----------------
__device__ __forceinline__ void mma_f16(float* c, const unsigned* a, unsigned b0, unsigned b1) {
    asm volatile(
        "mma.sync.aligned.m16n8k16.row.col.f32.f16.f16.f32 "
        "{%0,%1,%2,%3}, {%4,%5,%6,%7}, {%8,%9}, {%0,%1,%2,%3};\n"
        : "+f"(c[0]), "+f"(c[1]), "+f"(c[2]), "+f"(c[3])
        : "r"(a[0]), "r"(a[1]), "r"(a[2]), "r"(a[3]), "r"(b0), "r"(b1));
}
__device__ __forceinline__ void cp16(void* dst, const void* src) {
    unsigned d = (unsigned)__cvta_generic_to_shared(dst);
    asm volatile("cp.async.cg.shared.global [%0], [%1], 16;\n" :: "r"(d), "l"(src));
}
__device__ __forceinline__ void cp_commit() { asm volatile("cp.async.commit_group;\n"); }
__device__ __forceinline__ void cp_wait1()  { asm volatile("cp.async.wait_group 1;\n"); }

// ---------------- small kernels ----------------
__global__ void init_kernel() {
    int t = threadIdx.x;
    if (t < NE) { g_cnt[t] = 0; g_fill[t] = 0; }
}

__global__ void router_kernel(const float* __restrict__ x,
                              const float* __restrict__ wr,
                              const float* __restrict__ wsg) {
    int gw   = (blockIdx.x * blockDim.x + threadIdx.x) >> 5;
    int lane = threadIdx.x & 31;
    if (gw >= T_TOK) return;
    const float* xr = x + (size_t)gw * HD;
    float acc[NE];
#pragma unroll
    for (int e = 0; e < NE; e++) acc[e] = 0.f;
    float ag = 0.f;
    for (int h = lane; h < HD; h += 32) {
        float xv = xr[h];
        const float4* w = (const float4*)(wr + (size_t)h * NE);
        float4 w0 = w[0], w1 = w[1];
        acc[0] += xv * w0.x; acc[1] += xv * w0.y; acc[2] += xv * w0.z; acc[3] += xv * w0.w;
        acc[4] += xv * w1.x; acc[5] += xv * w1.y; acc[6] += xv * w1.z; acc[7] += xv * w1.w;
        ag += xv * wsg[h];
    }
#pragma unroll
    for (int o = 16; o > 0; o >>= 1) {
#pragma unroll
        for (int e = 0; e < NE; e++) acc[e] += __shfl_xor_sync(0xffffffffu, acc[e], o);
        ag += __shfl_xor_sync(0xffffffffu, ag, o);
    }
    if (lane == 0) {
        int i0 = 0; float v0 = acc[0];
#pragma unroll
        for (int e = 1; e < NE; e++) if (acc[e] > v0) { v0 = acc[e]; i0 = e; }
        int i1 = -1; float v1 = -1e30f;
#pragma unroll
        for (int e = 0; e < NE; e++) if (e != i0 && acc[e] > v1) { v1 = acc[e]; i1 = e; }
        float t  = __expf(v1 - v0);
        g_top_e[gw * 2]     = i0;
        g_top_e[gw * 2 + 1] = i1;
        g_top_p[gw * 2]     = 1.f / (1.f + t);
        g_top_p[gw * 2 + 1] = t / (1.f + t);
        atomicAdd(&g_cnt[i0], 1);
        atomicAdd(&g_cnt[i1], 1);
        g_gate[gw] = 1.f / (1.f + __expf(-ag));
    }
}

__global__ void scan_kernel() {
    if (threadIdx.x == 0 && blockIdx.x == 0) {
        int off = 0, nt = 0;
        for (int e = 0; e < NE; e++) {
            g_off[e] = off;
            int c = g_cnt[e];
            for (int r = 0; r < c; r += 128) {
                g_tile_e[nt]    = e;
                g_tile_row0[nt] = off + r;
                g_tile_rows[nt] = (c - r < 128) ? (c - r) : 128;
                nt++;
            }
            off = (off + c + 127) & ~127;
        }
        g_ntiles = nt;
    }
}

__global__ void scatter_kernel(const float* __restrict__ x) {
    int a = blockIdx.x;
    int t = a >> 1;
    __shared__ int srow;
    int   e = g_top_e[a];
    float p = g_top_p[a];
    if (threadIdx.x == 0) {
        int pos = atomicAdd(&g_fill[e], 1);
        int row = g_off[e] + pos;
        g_row_token[row] = t;
        srow = row;
    }
    __syncthreads();
    int row = srow;
    const float4* src = (const float4*)(x + (size_t)t * HD);
    __half2*      dst = (__half2*)(g_xin + (size_t)row * HD);
    for (int i = threadIdx.x; i < HD / 4; i += blockDim.x) {
        float4 v = src[i];
        dst[2 * i]     = __floats2half2_rn(v.x * p, v.y * p);
        dst[2 * i + 1] = __floats2half2_rn(v.z * p, v.w * p);
    }
}

// ---------------- fused prep: 4 weight transposes + x->fp16, ONE launch ----------------
__device__ __forceinline__ void trans_tile(const float* __restrict__ src,
                                           __half* __restrict__ dst,
                                           int K, int N, int nx, int ky) {
    __shared__ float t[32][33];
    int n0 = nx * 32, k0 = ky * 32;
    int tx = threadIdx.x, ty = threadIdx.y;
#pragma unroll
    for (int i = 0; i < 4; i++)
        t[ty + 8 * i][tx] = src[(size_t)(k0 + ty + 8 * i) * N + n0 + tx];
    __syncthreads();
#pragma unroll
    for (int i = 0; i < 4; i++)
        dst[(size_t)(n0 + ty + 8 * i) * K + k0 + tx] = __float2half_rn(t[tx][ty + 8 * i]);
}

#define P_WGU  45056   // 8 * (2816/32) * (2048/32)
#define P_WD   67584   // + 8 * (2048/32) * (1408/32)
#define P_WSGU 73216   // + 5632
#define P_WSD  76032   // + 2816
#define P_END  92416   // + 16384 (x cvt: one float4/thread)
__global__ void prep_kernel(const float* __restrict__ x,
                            const float* __restrict__ wgu,
                            const float* __restrict__ wd,
                            const float* __restrict__ wsgu,
                            const float* __restrict__ wsd) {
    int id = blockIdx.x;
    if (id < P_WGU) {
        int e = id / 5632, r = id % 5632;
        trans_tile(wgu + (size_t)e * HD * TWO_I, g_wgu_h + (size_t)e * TWO_I * HD,
                   HD, TWO_I, r % 88, r / 88);
    } else if (id < P_WD) {
        int id2 = id - P_WGU;
        int e = id2 / 2816, r = id2 % 2816;
        trans_tile(wd + (size_t)e * ID * HD, g_wd_h + (size_t)e * HD * ID,
                   ID, HD, r % 64, r / 64);
    } else if (id < P_WSGU) {
        int r = id - P_WD;
        trans_tile(wsgu, g_wsgu_h, HD, TWO_I, r % 88, r / 88);
    } else if (id < P_WSD) {
        int r = id - P_WSGU;
        trans_tile(wsd, g_wsd_h, ID, HD, r % 64, r / 64);
    } else {
        int i = (id - P_WSD) * 256 + threadIdx.y * 32 + threadIdx.x;
        float4 v = ((const float4*)x)[i];
        __half2* d = (__half2*)g_xh;
        d[2 * i]     = __floats2half2_rn(v.x, v.y);
        d[2 * i + 1] = __floats2half2_rn(v.z, v.w);
    }
}

// ---------------- GEMM1: fp16 m16n8k16, BM=128, dual BN=64 (g/u), BK=16 ----------------
__global__ __launch_bounds__(256, 2) void gemm1_kernel() {
    int bx = blockIdx.y;
    bool sh = (bx >= RT_TILES);
    if (!sh && bx >= g_ntiles) return;
    int row0;
    const __half *A, *Bt;
    __half* Hout;
    if (sh) {
        row0 = (bx - RT_TILES) * 128;
        A = g_xh; Bt = g_wsgu_h; Hout = g_shidden;
    } else {
        row0 = g_tile_row0[bx];
        A = g_xin;
        Bt = g_wgu_h + (size_t)g_tile_e[bx] * TWO_I * HD;
        Hout = g_hidden;
    }
    int n0 = blockIdx.x * 64;

    __shared__ __half As[2][128][STR];
    __shared__ __half Bg[2][64][STR];
    __shared__ __half Bu[2][64][STR];

    int tid = threadIdx.x, lane = tid & 31, warp = tid >> 5;
    int wm = warp >> 1, wn = warp & 1;

    float cg[2][4][4], cu[2][4][4];
#pragma unroll
    for (int i = 0; i < 2; i++)
#pragma unroll
        for (int j = 0; j < 4; j++)
#pragma unroll
            for (int q = 0; q < 4; q++) { cg[i][j][q] = 0.f; cu[i][j][q] = 0.f; }

    int ar = tid >> 1, ac = tid & 1;
    const __half* a_base = A + (size_t)(row0 + ar) * HD + ac * 8;
    int  br = (tid & 127) >> 1, bc = tid & 1;
    bool isu = tid >= 128;
    const __half* b_base = Bt + (size_t)((isu ? ID : 0) + n0 + br) * HD + bc * 8;

    cp16(&As[0][ar][ac * 8], a_base);
    cp16(isu ? &Bu[0][br][bc * 8] : &Bg[0][br][bc * 8], b_base);
    cp_commit();

    const int NIT = HD / 16;
    for (int it = 0; it < NIT; it++) {
        int cur = it & 1, nxt = cur ^ 1;
        if (it + 1 < NIT) {
            cp16(&As[nxt][ar][ac * 8], a_base + (it + 1) * 16);
            cp16(isu ? &Bu[nxt][br][bc * 8] : &Bg[nxt][br][bc * 8], b_base + (it + 1) * 16);
        }
        cp_commit();
        cp_wait1();
        __syncthreads();

        const unsigned* As32 = (const unsigned*)As[cur];
        const unsigned* Bg32 = (const unsigned*)Bg[cur];
        const unsigned* Bu32 = (const unsigned*)Bu[cur];
        unsigned a[2][4];
#pragma unroll
        for (int mt = 0; mt < 2; mt++) {
            int r = wm * 32 + mt * 16 + (lane >> 2);
            a[mt][0] = As32[r * 12 + (lane & 3)];
            a[mt][1] = As32[(r + 8) * 12 + (lane & 3)];
            a[mt][2] = As32[r * 12 + (lane & 3) + 4];
            a[mt][3] = As32[(r + 8) * 12 + (lane & 3) + 4];
        }
#pragma unroll
        for (int nt = 0; nt < 4; nt++) {
            int n = wn * 32 + nt * 8 + (lane >> 2);
            unsigned bg0 = Bg32[n * 12 + (lane & 3)], bg1 = Bg32[n * 12 + (lane & 3) + 4];
            unsigned bu0 = Bu32[n * 12 + (lane & 3)], bu1 = Bu32[n * 12 + (lane & 3) + 4];
#pragma unroll
            for (int mt = 0; mt < 2; mt++) {
                mma_f16(cg[mt][nt], a[mt], bg0, bg1);
                mma_f16(cu[mt][nt], a[mt], bu0, bu1);
            }
        }
        __syncthreads();
    }

#pragma unroll
    for (int mt = 0; mt < 2; mt++) {
#pragma unroll
        for (int nt = 0; nt < 4; nt++) {
            int rb = row0 + wm * 32 + mt * 16 + (lane >> 2);
            int nb = n0 + wn * 32 + nt * 8 + (lane & 3) * 2;
#pragma unroll
            for (int q = 0; q < 4; q++) {
                int rr = rb + ((q >= 2) ? 8 : 0);
                int nn = nb + (q & 1);
                float g = cg[mt][nt][q], u = cu[mt][nt][q];
                float s = 1.f / (1.f + __expf(-g));
                Hout[(size_t)rr * ID + nn] = __float2half_rn(g * s * u);
            }
        }
    }
}

// ---------------- GEMM2: fp16 m16n8k16, BM=128, BN=128, BK=16, atomic epilogue ----------------
__global__ __launch_bounds__(256, 2) void gemm2_kernel(float* __restrict__ out) {
    int bx = blockIdx.y;
    bool sh = (bx >= RT_TILES);
    if (!sh && bx >= g_ntiles) return;
    int row0, vrows;
    const __half *A, *Bt;
    if (sh) {
        row0 = (bx - RT_TILES) * 128; vrows = 128;
        A = g_shidden; Bt = g_wsd_h;
    } else {
        row0 = g_tile_row0[bx];
        vrows = g_tile_rows[bx];
        A = g_hidden;
        Bt = g_wd_h + (size_t)g_tile_e[bx] * HD * ID;
    }
    int col0 = blockIdx.x * 128;

    __shared__ __half As[2][128][STR];
    __shared__ __half Bs[2][128][STR];

    int tid = threadIdx.x, lane = tid & 31, warp = tid >> 5;
    int wm = warp >> 1, wn = warp & 1;

    float c[2][8][4];
#pragma unroll
    for (int i = 0; i < 2; i++)
#pragma unroll
        for (int j = 0; j < 8; j++)
#pragma unroll
            for (int q = 0; q < 4; q++) c[i][j][q] = 0.f;

    int r2 = tid >> 1, c2 = tid & 1;
    const __half* a_base = A  + (size_t)(row0 + r2) * ID + c2 * 8;
    const __half* b_base = Bt + (size_t)(col0 + r2) * ID + c2 * 8;

    cp16(&As[0][r2][c2 * 8], a_base);
    cp16(&Bs[0][r2][c2 * 8], b_base);
    cp_commit();

    const int NIT = ID / 16;
    for (int it = 0; it < NIT; it++) {
        int cur = it & 1, nxt = cur ^ 1;
        if (it + 1 < NIT) {
            cp16(&As[nxt][r2][c2 * 8], a_base + (it + 1) * 16);
            cp16(&Bs[nxt][r2][c2 * 8], b_base + (it + 1) * 16);
        }
        cp_commit();
        cp_wait1();
        __syncthreads();

        const unsigned* As32 = (const unsigned*)As[cur];
        const unsigned* Bs32 = (const unsigned*)Bs[cur];
        unsigned a[2][4];
#pragma unroll
        for (int mt = 0; mt < 2; mt++) {
            int r = wm * 32 + mt * 16 + (lane >> 2);
            a[mt][0] = As32[r * 12 + (lane & 3)];
            a[mt][1] = As32[(r + 8) * 12 + (lane & 3)];
            a[mt][2] = As32[r * 12 + (lane & 3) + 4];
            a[mt][3] = As32[(r + 8) * 12 + (lane & 3) + 4];
        }
#pragma unroll
        for (int nt = 0; nt < 8; nt++) {
            int n = wn * 64 + nt * 8 + (lane >> 2);
            unsigned b0 = Bs32[n * 12 + (lane & 3)], b1 = Bs32[n * 12 + (lane & 3) + 4];
#pragma unroll
            for (int mt = 0; mt < 2; mt++) mma_f16(c[mt][nt], a[mt], b0, b1);
        }
        __syncthreads();
    }

#pragma unroll
    for (int mt = 0; mt < 2; mt++) {
#pragma unroll
        for (int nt = 0; nt < 8; nt++) {
            int lr0 = wm * 32 + mt * 16 + (lane >> 2);
            int nb  = col0 + wn * 64 + nt * 8 + (lane & 3) * 2;
#pragma unroll
            for (int q = 0; q < 4; q++) {
                int lr = lr0 + ((q >= 2) ? 8 : 0);
                int nn = nb + (q & 1);
                float v = c[mt][nt][q];
                if (lr < vrows) {
                    if (sh) {
                        int t = row0 + lr;
                        atomicAdd(&out[(size_t)t * HD + nn], g_gate[t] * v);
                    } else {
                        int t = g_row_token[row0 + lr];
                        atomicAdd(&out[(size_t)t * HD + nn], v);
                    }
                }
            }
        }
    }
}

// ---------------- launch ----------------
extern "C" void kernel_launch(void* const* d_in, const int* in_sizes, int n_in,
                              void* d_out, int out_size) {
    const float* x    = (const float*)d_in[0];
    const float* wr   = (const float*)d_in[1];
    const float* wgu  = (const float*)d_in[2];
    const float* wd   = (const float*)d_in[3];
    const float* wsgu = (const float*)d_in[4];
    const float* wsd  = (const float*)d_in[5];
    const float* wsg  = (const float*)d_in[6];
    float* out = (float*)d_out;

    init_kernel<<<1, 32>>>();                              // launch 0
    router_kernel<<<T_TOK / 8, 256>>>(x, wr, wsg);         // 1
    scan_kernel<<<1, 1>>>();                               // 2
    scatter_kernel<<<NA, 256>>>(x);                        // 3
    prep_kernel<<<P_END, dim3(32, 8)>>>(x, wgu, wd, wsgu, wsd);  // 4
    cudaMemsetAsync(out, 0, (size_t)out_size * sizeof(float), 0);

    gemm1_kernel<<<dim3(ID / 64, RT_TILES + T_TOK / 128), 256>>>();        // 5 (ncu target)
    gemm2_kernel<<<dim3(HD / 128, RT_TILES + T_TOK / 128), 256>>>(out);    // 6
}

// round 13
// speedup vs baseline: 2.1643x; 1.3833x over previous
#include <cuda_runtime.h>
#include <cuda_fp16.h>
#include <math.h>

#define T_TOK 8192
#define HD    2048
#define NE    8
#define ID    1408
#define TWO_I 2816
#define NA    16384
#define NA_PAD 17408   // expert regions 128-aligned (R4 fix)
#define MAX_TILES 144
#define RT_TILES 136
#define NSTG 4
#define STGB 12288     // bytes per stage: A 6144 + B 6144 (48B rows)

// ---------------- scratch ----------------
__device__ __half g_xin[(size_t)NA_PAD * HD];
__device__ __half g_hidden[(size_t)NA_PAD * ID];
__device__ __half g_shidden[(size_t)T_TOK * ID];
__device__ __half g_xh[(size_t)T_TOK * HD];
__device__ __half g_wgu_h[(size_t)NE * TWO_I * HD];
__device__ __half g_wd_h[(size_t)NE * HD * ID];
__device__ __half g_wsgu_h[(size_t)TWO_I * HD];
__device__ __half g_wsd_h[(size_t)HD * ID];
__device__ int   g_top_e[NA];
__device__ float g_top_p[NA];
__device__ float g_gate[T_TOK];
__device__ int   g_cnt[NE], g_off[NE], g_fill[NE];
__device__ int   g_row_token[NA_PAD];
__device__ int   g_tile_e[MAX_TILES], g_tile_row0[MAX_TILES], g_tile_rows[MAX_TILES];
__device__ int   g_ntiles;

// ---------------- helpers ----------------
__device__ __forceinline__ void mma_f16(float* c, const unsigned* a, unsigned b0, unsigned b1) {
    asm volatile(
        "mma.sync.aligned.m16n8k16.row.col.f32.f16.f16.f32 "
        "{%0,%1,%2,%3}, {%4,%5,%6,%7}, {%8,%9}, {%0,%1,%2,%3};\n"
        : "+f"(c[0]), "+f"(c[1]), "+f"(c[2]), "+f"(c[3])
        : "r"(a[0]), "r"(a[1]), "r"(a[2]), "r"(a[3]), "r"(b0), "r"(b1));
}
__device__ __forceinline__ void ldsm4(unsigned* r, unsigned addr) {
    asm volatile("ldmatrix.sync.aligned.m8n8.x4.shared.b16 {%0,%1,%2,%3}, [%4];"
                 : "=r"(r[0]), "=r"(r[1]), "=r"(r[2]), "=r"(r[3]) : "r"(addr));
}
__device__ __forceinline__ void cp16s(unsigned dst, const void* src) {
    asm volatile("cp.async.cg.shared.global [%0], [%1], 16;\n" :: "r"(dst), "l"(src));
}
__device__ __forceinline__ void cp_commit() { asm volatile("cp.async.commit_group;\n"); }
__device__ __forceinline__ void cp_wait2()  { asm volatile("cp.async.wait_group 2;\n"); }

// ---------------- small kernels ----------------
__global__ void init_kernel() {
    int t = threadIdx.x;
    if (t < NE) { g_cnt[t] = 0; g_fill[t] = 0; }
}

__global__ void router_kernel(const float* __restrict__ x,
                              const float* __restrict__ wr,
                              const float* __restrict__ wsg) {
    int gw   = (blockIdx.x * blockDim.x + threadIdx.x) >> 5;
    int lane = threadIdx.x & 31;
    if (gw >= T_TOK) return;
    const float* xr = x + (size_t)gw * HD;
    float acc[NE];
#pragma unroll
    for (int e = 0; e < NE; e++) acc[e] = 0.f;
    float ag = 0.f;
    for (int h = lane; h < HD; h += 32) {
        float xv = xr[h];
        const float4* w = (const float4*)(wr + (size_t)h * NE);
        float4 w0 = w[0], w1 = w[1];
        acc[0] += xv * w0.x; acc[1] += xv * w0.y; acc[2] += xv * w0.z; acc[3] += xv * w0.w;
        acc[4] += xv * w1.x; acc[5] += xv * w1.y; acc[6] += xv * w1.z; acc[7] += xv * w1.w;
        ag += xv * wsg[h];
    }
#pragma unroll
    for (int o = 16; o > 0; o >>= 1) {
#pragma unroll
        for (int e = 0; e < NE; e++) acc[e] += __shfl_xor_sync(0xffffffffu, acc[e], o);
        ag += __shfl_xor_sync(0xffffffffu, ag, o);
    }
    if (lane == 0) {
        int i0 = 0; float v0 = acc[0];
#pragma unroll
        for (int e = 1; e < NE; e++) if (acc[e] > v0) { v0 = acc[e]; i0 = e; }
        int i1 = -1; float v1 = -1e30f;
#pragma unroll
        for (int e = 0; e < NE; e++) if (e != i0 && acc[e] > v1) { v1 = acc[e]; i1 = e; }
        float t  = __expf(v1 - v0);
        g_top_e[gw * 2]     = i0;
        g_top_e[gw * 2 + 1] = i1;
        g_top_p[gw * 2]     = 1.f / (1.f + t);
        g_top_p[gw * 2 + 1] = t / (1.f + t);
        atomicAdd(&g_cnt[i0], 1);
        atomicAdd(&g_cnt[i1], 1);
        g_gate[gw] = 1.f / (1.f + __expf(-ag));
    }
}

__global__ void scan_kernel() {
    if (threadIdx.x == 0 && blockIdx.x == 0) {
        int off = 0, nt = 0;
        for (int e = 0; e < NE; e++) {
            g_off[e] = off;
            int c = g_cnt[e];
            for (int r = 0; r < c; r += 128) {
                g_tile_e[nt]    = e;
                g_tile_row0[nt] = off + r;
                g_tile_rows[nt] = (c - r < 128) ? (c - r) : 128;
                nt++;
            }
            off = (off + c + 127) & ~127;
        }
        g_ntiles = nt;
    }
}

__global__ void scatter_kernel(const float* __restrict__ x) {
    int a = blockIdx.x;
    int t = a >> 1;
    __shared__ int srow;
    int   e = g_top_e[a];
    float p = g_top_p[a];
    if (threadIdx.x == 0) {
        int pos = atomicAdd(&g_fill[e], 1);
        int row = g_off[e] + pos;
        g_row_token[row] = t;
        srow = row;
    }
    __syncthreads();
    int row = srow;
    const float4* src = (const float4*)(x + (size_t)t * HD);
    __half2*      dst = (__half2*)(g_xin + (size_t)row * HD);
    for (int i = threadIdx.x; i < HD / 4; i += blockDim.x) {
        float4 v = src[i];
        dst[2 * i]     = __floats2half2_rn(v.x * p, v.y * p);
        dst[2 * i + 1] = __floats2half2_rn(v.z * p, v.w * p);
    }
}

// ---------------- fused prep: 4 weight transposes + x->fp16 ----------------
__device__ __forceinline__ void trans_tile(const float* __restrict__ src,
                                           __half* __restrict__ dst,
                                           int K, int N, int nx, int ky) {
    __shared__ float t[32][33];
    int n0 = nx * 32, k0 = ky * 32;
    int tx = threadIdx.x, ty = threadIdx.y;
#pragma unroll
    for (int i = 0; i < 4; i++)
        t[ty + 8 * i][tx] = src[(size_t)(k0 + ty + 8 * i) * N + n0 + tx];
    __syncthreads();
#pragma unroll
    for (int i = 0; i < 4; i++)
        dst[(size_t)(n0 + ty + 8 * i) * K + k0 + tx] = __float2half_rn(t[tx][ty + 8 * i]);
}

#define P_WGU  45056
#define P_WD   67584
#define P_WSGU 73216
#define P_WSD  76032
#define P_END  92416
__global__ void prep_kernel(const float* __restrict__ x,
                            const float* __restrict__ wgu,
                            const float* __restrict__ wd,
                            const float* __restrict__ wsgu,
                            const float* __restrict__ wsd) {
    int id = blockIdx.x;
    if (id < P_WGU) {
        int e = id / 5632, r = id % 5632;
        trans_tile(wgu + (size_t)e * HD * TWO_I, g_wgu_h + (size_t)e * TWO_I * HD,
                   HD, TWO_I, r % 88, r / 88);
    } else if (id < P_WD) {
        int id2 = id - P_WGU;
        int e = id2 / 2816, r = id2 % 2816;
        trans_tile(wd + (size_t)e * ID * HD, g_wd_h + (size_t)e * HD * ID,
                   ID, HD, r % 64, r / 64);
    } else if (id < P_WSGU) {
        int r = id - P_WD;
        trans_tile(wsgu, g_wsgu_h, HD, TWO_I, r % 88, r / 88);
    } else if (id < P_WSD) {
        int r = id - P_WSGU;
        trans_tile(wsd, g_wsd_h, ID, HD, r % 64, r / 64);
    } else {
        int i = (id - P_WSD) * 256 + threadIdx.y * 32 + threadIdx.x;
        float4 v = ((const float4*)x)[i];
        __half2* d = (__half2*)g_xh;
        d[2 * i]     = __floats2half2_rn(v.x, v.y);
        d[2 * i + 1] = __floats2half2_rn(v.z, v.w);
    }
}

// ---------------- GEMM1: fp16, BM=128, dual BN=64 (g/u), BK=16, ldmatrix + 4-stage ----------------
// stage layout (bytes): A [0,6144)  Bg [6144,9216)  Bu [9216,12288)
__global__ __launch_bounds__(256, 2) void gemm1_kernel() {
    int bx = blockIdx.y;
    bool sh = (bx >= RT_TILES);
    if (!sh && bx >= g_ntiles) return;
    int row0;
    const __half *A, *Bt;
    __half* Hout;
    if (sh) {
        row0 = (bx - RT_TILES) * 128;
        A = g_xh; Bt = g_wsgu_h; Hout = g_shidden;
    } else {
        row0 = g_tile_row0[bx];
        A = g_xin;
        Bt = g_wgu_h + (size_t)g_tile_e[bx] * TWO_I * HD;
        Hout = g_hidden;
    }
    int n0 = blockIdx.x * 64;

    __shared__ __half smem[NSTG * STGB / 2];
    unsigned sb = (unsigned)__cvta_generic_to_shared(smem);

    int tid = threadIdx.x, lane = tid & 31, warp = tid >> 5;
    int wm = warp >> 1, wn = warp & 1;

    // loader mapping: A 1 cp16/thread; B 1 cp16/thread (0-127 gate, 128-255 up)
    int ar_ = tid >> 1, ac_ = (tid & 1) * 8;
    const __half* a_src = A + (size_t)(row0 + ar_) * HD + ac_;
    unsigned a_dst = sb + ar_ * 48 + ac_ * 2;
    int br_ = (tid & 127) >> 1, bc_ = (tid & 1) * 8;
    bool isu = tid >= 128;
    const __half* b_src = Bt + (size_t)((isu ? ID : 0) + n0 + br_) * HD + bc_;
    unsigned b_dst = sb + (isu ? 9216 : 6144) + br_ * 48 + bc_ * 2;

    // fragment smem offsets (bytes within stage)
    int g8 = lane >> 3, r8 = lane & 7;
    unsigned a_frag[2], bg_frag[2], bu_frag[2];
#pragma unroll
    for (int mt = 0; mt < 2; mt++)
        a_frag[mt] = sb + ((wm * 32 + mt * 16 + ((g8 & 1) << 3) + r8) * 24 + ((g8 >> 1) << 3)) * 2;
#pragma unroll
    for (int p = 0; p < 2; p++) {
        unsigned ro = ((wn * 32 + p * 16 + ((g8 >> 1) << 3) + r8) * 24 + ((g8 & 1) << 3)) * 2;
        bg_frag[p] = sb + 6144 + ro;
        bu_frag[p] = sb + 9216 + ro;
    }

    float cg[2][4][4], cu[2][4][4];
#pragma unroll
    for (int i = 0; i < 2; i++)
#pragma unroll
        for (int j = 0; j < 4; j++)
#pragma unroll
            for (int q = 0; q < 4; q++) { cg[i][j][q] = 0.f; cu[i][j][q] = 0.f; }

    const int NIT = HD / 16;
#pragma unroll 1
    for (int s = 0; s < NSTG - 1; s++) {
        unsigned off = s * STGB;
        cp16s(a_dst + off, a_src + s * 16);
        cp16s(b_dst + off, b_src + s * 16);
        cp_commit();
    }
#pragma unroll 1
    for (int it = 0; it < NIT; it++) {
        cp_wait2();
        __syncthreads();
        int lt = it + NSTG - 1;
        if (lt < NIT) {
            unsigned off = (lt & (NSTG - 1)) * STGB;
            cp16s(a_dst + off, a_src + lt * 16);
            cp16s(b_dst + off, b_src + lt * 16);
        }
        cp_commit();

        unsigned soff = (it & (NSTG - 1)) * STGB;
        unsigned a[2][4];
        ldsm4(a[0], a_frag[0] + soff);
        ldsm4(a[1], a_frag[1] + soff);
#pragma unroll
        for (int p = 0; p < 2; p++) {
            unsigned bg[4], bu[4];
            ldsm4(bg, bg_frag[p] + soff);
            ldsm4(bu, bu_frag[p] + soff);
#pragma unroll
            for (int j = 0; j < 2; j++) {
                int nt = 2 * p + j;
#pragma unroll
                for (int mt = 0; mt < 2; mt++) {
                    mma_f16(cg[mt][nt], a[mt], bg[2 * j], bg[2 * j + 1]);
                    mma_f16(cu[mt][nt], a[mt], bu[2 * j], bu[2 * j + 1]);
                }
            }
        }
    }

#pragma unroll
    for (int mt = 0; mt < 2; mt++) {
#pragma unroll
        for (int nt = 0; nt < 4; nt++) {
            int rb = row0 + wm * 32 + mt * 16 + (lane >> 2);
            int nb = n0 + wn * 32 + nt * 8 + (lane & 3) * 2;
#pragma unroll
            for (int q = 0; q < 4; q++) {
                int rr = rb + ((q >= 2) ? 8 : 0);
                int nn = nb + (q & 1);
                float g = cg[mt][nt][q], u = cu[mt][nt][q];
                float s = 1.f / (1.f + __expf(-g));
                Hout[(size_t)rr * ID + nn] = __float2half_rn(g * s * u);
            }
        }
    }
}

// ---------------- GEMM2: fp16, BM=128, BN=128, BK=16, ldmatrix + 4-stage ----------------
// SH=true: shared expert, plain stores (covers all elements). SH=false: routed, atomicAdd.
template <bool SH>
__global__ __launch_bounds__(256, 2) void gemm2_kernel(float* __restrict__ out) {
    int bx = blockIdx.y;
    int row0, vrows;
    const __half *A, *Bt;
    if (SH) {
        row0 = bx * 128; vrows = 128;
        A = g_shidden; Bt = g_wsd_h;
    } else {
        if (bx >= g_ntiles) return;
        row0 = g_tile_row0[bx];
        vrows = g_tile_rows[bx];
        A = g_hidden;
        Bt = g_wd_h + (size_t)g_tile_e[bx] * HD * ID;
    }
    int col0 = blockIdx.x * 128;

    __shared__ __half smem[NSTG * STGB / 2];
    unsigned sb = (unsigned)__cvta_generic_to_shared(smem);

    int tid = threadIdx.x, lane = tid & 31, warp = tid >> 5;
    int wm = warp >> 1, wn = warp & 1;

    int lr_ = tid >> 1, lc = (tid & 1) * 8;
    const __half* a_src = A  + (size_t)(row0 + lr_) * ID + lc;
    const __half* b_src = Bt + (size_t)(col0 + lr_) * ID + lc;
    unsigned a_dst = sb + lr_ * 48 + lc * 2;
    unsigned b_dst = a_dst + 6144;

    int g8 = lane >> 3, r8 = lane & 7;
    unsigned a_frag[2], b_frag[4];
#pragma unroll
    for (int mt = 0; mt < 2; mt++)
        a_frag[mt] = sb + ((wm * 32 + mt * 16 + ((g8 & 1) << 3) + r8) * 24 + ((g8 >> 1) << 3)) * 2;
#pragma unroll
    for (int p = 0; p < 4; p++)
        b_frag[p] = sb + 6144 +
                    ((wn * 64 + p * 16 + ((g8 >> 1) << 3) + r8) * 24 + ((g8 & 1) << 3)) * 2;

    float c[2][8][4];
#pragma unroll
    for (int i = 0; i < 2; i++)
#pragma unroll
        for (int j = 0; j < 8; j++)
#pragma unroll
            for (int q = 0; q < 4; q++) c[i][j][q] = 0.f;

    const int NIT = ID / 16;
#pragma unroll 1
    for (int s = 0; s < NSTG - 1; s++) {
        unsigned off = s * STGB;
        cp16s(a_dst + off, a_src + s * 16);
        cp16s(b_dst + off, b_src + s * 16);
        cp_commit();
    }
#pragma unroll 1
    for (int it = 0; it < NIT; it++) {
        cp_wait2();
        __syncthreads();
        int lt = it + NSTG - 1;
        if (lt < NIT) {
            unsigned off = (lt & (NSTG - 1)) * STGB;
            cp16s(a_dst + off, a_src + lt * 16);
            cp16s(b_dst + off, b_src + lt * 16);
        }
        cp_commit();

        unsigned soff = (it & (NSTG - 1)) * STGB;
        unsigned a[2][4];
        ldsm4(a[0], a_frag[0] + soff);
        ldsm4(a[1], a_frag[1] + soff);
#pragma unroll
        for (int p = 0; p < 4; p++) {
            unsigned b[4];
            ldsm4(b, b_frag[p] + soff);
#pragma unroll
            for (int j = 0; j < 2; j++) {
#pragma unroll
                for (int mt = 0; mt < 2; mt++)
                    mma_f16(c[mt][2 * p + j], a[mt], b[2 * j], b[2 * j + 1]);
            }
        }
    }

#pragma unroll
    for (int mt = 0; mt < 2; mt++) {
#pragma unroll
        for (int nt = 0; nt < 8; nt++) {
            int lr0 = wm * 32 + mt * 16 + (lane >> 2);
            int nb  = col0 + wn * 64 + nt * 8 + (lane & 3) * 2;
#pragma unroll
            for (int q = 0; q < 4; q++) {
                int lr = lr0 + ((q >= 2) ? 8 : 0);
                int nn = nb + (q & 1);
                float v = c[mt][nt][q];
                if (SH) {
                    int t = row0 + lr;
                    out[(size_t)t * HD + nn] = g_gate[t] * v;
                } else if (lr < vrows) {
                    int t = g_row_token[row0 + lr];
                    atomicAdd(&out[(size_t)t * HD + nn], v);
                }
            }
        }
    }
}

// ---------------- launch ----------------
extern "C" void kernel_launch(void* const* d_in, const int* in_sizes, int n_in,
                              void* d_out, int out_size) {
    const float* x    = (const float*)d_in[0];
    const float* wr   = (const float*)d_in[1];
    const float* wgu  = (const float*)d_in[2];
    const float* wd   = (const float*)d_in[3];
    const float* wsgu = (const float*)d_in[4];
    const float* wsd  = (const float*)d_in[5];
    const float* wsg  = (const float*)d_in[6];
    float* out = (float*)d_out;

    init_kernel<<<1, 32>>>();                                    // 0
    router_kernel<<<T_TOK / 8, 256>>>(x, wr, wsg);               // 1
    scan_kernel<<<1, 1>>>();                                     // 2
    scatter_kernel<<<NA, 256>>>(x);                              // 3
    prep_kernel<<<P_END, dim3(32, 8)>>>(x, wgu, wd, wsgu, wsd);  // 4

    gemm1_kernel<<<dim3(ID / 64, RT_TILES + T_TOK / 128), 256>>>();      // 5 (ncu target)
    // shared gemm2 STORES gate*shared (every out element) -> no memset needed
    gemm2_kernel<true><<<dim3(HD / 128, T_TOK / 128), 256>>>(out);       // 6
    // routed gemm2 accumulates on top (ordered by stream)
    gemm2_kernel<false><<<dim3(HD / 128, RT_TILES), 256>>>(out);         // 7
}